// round 1
// baseline (speedup 1.0000x reference)
#include <cuda_runtime.h>
#include <math.h>
#include <stdint.h>

#define T_STEPS 2048
#define BATCH   64
#define HID     256
#define GATE4   1024
#define NG      (BATCH*HID)          /* 16384 */
#define REC_BLOCKS 128
#define REC_THREADS 256
#define HPAD    264                  /* padded row stride (floats), 16B-aligned */
#define REC_SMEM ((64*HPAD + 8*64)*4)

/* Scratch (device globals: no allocation allowed in kernel_launch) */
__device__ float g_xg[134217728];    /* [T][B][4H] precomputed input gates: 512 MB */
__device__ float g_h[2][NG];         /* double-buffered recurrent h, layout [b][j] */
__device__ unsigned g_bar;           /* monotonic grid barrier counter */
__device__ unsigned g_done;          /* end-of-kernel reset rendezvous */

__device__ __forceinline__ float dot4(float4 a, float4 b){
  return a.x*b.x + a.y*b.y + a.z*b.z + a.w*b.w;
}

/* ---------------- Kernel A: x_gates = input @ W_ih^T + b_ih + b_hh ----------------
 * A: [M=131072, K=256] row-major (input), W: [N=1024, K=256] row-major (W_ih).
 * BM=128, BN=64, BK=16; 256 threads (16x16); TM=8, TN=4 -> 32 accums/thread.
 * FMA:LDS-element ratio = 32:12 -> FMA-bound on the 128B/cyc smem datapath. */
__global__ void __launch_bounds__(256, 2) xgates_gemm(
    const float* __restrict__ A, const float* __restrict__ W,
    const float* __restrict__ bih, const float* __restrict__ bhh)
{
  __shared__ float a_t[16][132];   /* [k][m], padded */
  __shared__ float b_t[16][68];    /* [k][n], padded */
  const int tid = threadIdx.x;
  const int bx = blockIdx.x, by = blockIdx.y;
  const int tx = tid & 15, ty = tid >> 4;

  float acc[8][4];
  #pragma unroll
  for (int m=0;m<8;m++)
    #pragma unroll
    for (int n=0;n<4;n++) acc[m][n]=0.f;

  const float* Ab = A + (size_t)by*128*256;
  const float* Wb = W + (size_t)bx*64*256;

  for (int kt=0; kt<16; ++kt){
    const int k0 = kt*16;
    /* stage A tile 128x16 (512 float4, 2 per thread), transposed into [k][m] */
    #pragma unroll
    for (int r=0;r<2;r++){
      int idx = tid + r*256;
      int row = idx >> 2, kq = idx & 3;
      float4 v = *(const float4*)(Ab + (size_t)row*256 + k0 + kq*4);
      a_t[kq*4+0][row]=v.x; a_t[kq*4+1][row]=v.y;
      a_t[kq*4+2][row]=v.z; a_t[kq*4+3][row]=v.w;
    }
    /* stage W tile 64x16 (256 float4, 1 per thread), transposed into [k][n] */
    {
      int n = tid >> 2, kq = tid & 3;
      float4 v = *(const float4*)(Wb + (size_t)n*256 + k0 + kq*4);
      b_t[kq*4+0][n]=v.x; b_t[kq*4+1][n]=v.y;
      b_t[kq*4+2][n]=v.z; b_t[kq*4+3][n]=v.w;
    }
    __syncthreads();
    #pragma unroll
    for (int k=0;k<16;k++){
      float af[8], bf[4];
      *(float4*)(af)   = *(const float4*)&a_t[k][ty*8];
      *(float4*)(af+4) = *(const float4*)&a_t[k][ty*8+4];
      *(float4*)(bf)   = *(const float4*)&b_t[k][tx*4];
      #pragma unroll
      for (int m=0;m<8;m++)
        #pragma unroll
        for (int n=0;n<4;n++)
          acc[m][n] += af[m]*bf[n];
    }
    __syncthreads();
  }

  const int gn = bx*64 + tx*4;
  const float bb0 = bih[gn+0]+bhh[gn+0];
  const float bb1 = bih[gn+1]+bhh[gn+1];
  const float bb2 = bih[gn+2]+bhh[gn+2];
  const float bb3 = bih[gn+3]+bhh[gn+3];
  #pragma unroll
  for (int m=0;m<8;m++){
    int gm = by*128 + ty*8 + m;
    float4 o = make_float4(acc[m][0]+bb0, acc[m][1]+bb1, acc[m][2]+bb2, acc[m][3]+bb3);
    *(float4*)(g_xg + (size_t)gm*GATE4 + gn) = o;
  }
}

/* ---------------- Kernel B: persistent recurrence ----------------
 * 128 blocks (<= 148 SMs, guaranteed co-resident), 256 threads.
 * Block owns j0=2*blk, j1=2*blk+1 (8 gate rows of W_hh, held in REGISTERS:
 * warp = (j_local, 16-batch group); lane lg=lane&15 owns k in {lg*4+64q+e}).
 * Per step: stage h (global [b][j] -> smem [b][k], coalesced, __ldcg),
 * 64 FFMA per lane per 2-batch pass, 4-stage shfl reduce over 16 lanes,
 * epilogue (tid<128 owns (b, j_local); c stays in a register), grid barrier. */
__global__ void __launch_bounds__(REC_THREADS) lstm_rec(
    const float* __restrict__ h0, const float* __restrict__ c0,
    const float* __restrict__ W_hh, float* __restrict__ out)
{
  extern __shared__ float sm[];
  float* h_sm     = sm;             /* 64 x HPAD */
  float* gates_sm = sm + 64*HPAD;   /* 8 x 64   */

  const int tid  = threadIdx.x;
  const int blk  = blockIdx.x;
  const int wid  = tid >> 5, lane = tid & 31;
  const int rg   = wid & 1;         /* which j of the pair this warp computes */
  const int bgI  = wid >> 1;        /* 16-batch group */
  const int lg   = lane & 15, bg = lane >> 4;
  const int jw   = 2*blk + rg;

  /* W_hh slice -> registers: wr[gate][q] covers k = lg*4 + 64*q .. +3 */
  float4 wr[4][4];
  #pragma unroll
  for (int gi=0; gi<4; ++gi)
    #pragma unroll
    for (int q=0; q<4; ++q)
      wr[gi][q] = *(const float4*)(W_hh + (size_t)(gi*HID + jw)*HID + lg*4 + 64*q);

  /* epilogue ownership: thread (tid<128) owns (b=eb, j=2*blk+ejl); c in reg */
  const int eb = tid & 63, ejl = (tid >> 6) & 1;
  const int ej = 2*blk + ejl;
  float c_reg = 0.f;
  if (tid < 128) c_reg = c0[eb*HID + ej];

  for (int t=0; t<T_STEPS; ++t){
    /* prefetch this step's x-gate contribution (latency hidden by staging+compute) */
    float xg0=0.f, xg1=0.f, xg2=0.f, xg3=0.f;
    if (tid < 128){
      const float* xp = g_xg + ((size_t)t*BATCH + eb)*GATE4 + ej;
      xg0 = xp[0]; xg1 = xp[HID]; xg2 = xp[2*HID]; xg3 = xp[3*HID];
    }

    /* stage h: coalesced float4 global reads, conflict-free smem writes.
     * __ldcg: h is rewritten by other SMs every step; L1 would go stale. */
    const float4* hsrc = (const float4*)((t==0) ? h0 : g_h[t & 1]);
    #pragma unroll
    for (int i=0;i<16;i++){
      int fi = tid + i*256;                 /* f4 index, 0..4095 */
      float4 v = __ldcg(hsrc + fi);
      int b = fi >> 6, c = fi & 63;
      *(float4*)(h_sm + b*HPAD + c*4) = v;
    }
    __syncthreads();

    /* compute: 8 passes of 2 batches */
    const int bbase = bgI*16;
    #pragma unroll 2
    for (int p=0;p<8;p++){
      int b = bbase + p*2 + bg;
      const float* hr = h_sm + b*HPAD + lg*4;
      float4 hv0 = *(const float4*)(hr);
      float4 hv1 = *(const float4*)(hr+64);
      float4 hv2 = *(const float4*)(hr+128);
      float4 hv3 = *(const float4*)(hr+192);
      float a0 = dot4(wr[0][0],hv0)+dot4(wr[0][1],hv1)+dot4(wr[0][2],hv2)+dot4(wr[0][3],hv3);
      float a1 = dot4(wr[1][0],hv0)+dot4(wr[1][1],hv1)+dot4(wr[1][2],hv2)+dot4(wr[1][3],hv3);
      float a2 = dot4(wr[2][0],hv0)+dot4(wr[2][1],hv1)+dot4(wr[2][2],hv2)+dot4(wr[2][3],hv3);
      float a3 = dot4(wr[3][0],hv0)+dot4(wr[3][1],hv1)+dot4(wr[3][2],hv2)+dot4(wr[3][3],hv3);
      /* reduce over the 16 k-lanes (bg bit = lane bit 4, untouched by masks 1..8) */
      #pragma unroll
      for (int m=1;m<16;m<<=1){
        a0 += __shfl_xor_sync(0xffffffffu, a0, m);
        a1 += __shfl_xor_sync(0xffffffffu, a1, m);
        a2 += __shfl_xor_sync(0xffffffffu, a2, m);
        a3 += __shfl_xor_sync(0xffffffffu, a3, m);
      }
      if (lg == 0){
        float* gs = gates_sm + (rg*4)*64 + b;
        gs[0] = a0; gs[64] = a1; gs[128] = a2; gs[192] = a3;
      }
    }
    __syncthreads();

    /* epilogue: gate nonlinearities + cell/hidden update */
    if (tid < 128){
      const float* gs = gates_sm + (ejl*4)*64 + eb;
      float pi = gs[0]   + xg0;
      float pf = gs[64]  + xg1;
      float pg = gs[128] + xg2;
      float po = gs[192] + xg3;
      float ii = 1.f/(1.f+expf(-pi));
      float ff = 1.f/(1.f+expf(-pf));
      float gg = tanhf(pg);
      float oo = 1.f/(1.f+expf(-po));
      c_reg = ff*c_reg + ii*gg;
      float hn = oo * tanhf(c_reg);
      g_h[(t+1)&1][eb*HID + ej] = hn;
      out[(size_t)t*NG + eb*HID + ej] = hn;
      if (t == T_STEPS-1){
        out[(size_t)T_STEPS*NG + eb*HID + ej]      = hn;   /* h_T */
        out[(size_t)T_STEPS*NG + NG + eb*HID + ej] = c_reg; /* c_T */
      }
    }

    /* grid barrier: monotonic counter, release via threadfence */
    __threadfence();
    __syncthreads();
    if (tid == 0){
      atomicAdd(&g_bar, 1u);
      const unsigned target = (unsigned)(t+1) * REC_BLOCKS;
      while (*((volatile unsigned*)&g_bar) < target) { }
      __threadfence();
    }
    __syncthreads();
  }

  /* reset counters for the next graph replay: last block to finish does it,
   * and it can only be last after every block has passed the final spin. */
  if (tid == 0){
    unsigned prev = atomicAdd(&g_done, 1u);
    if (prev == REC_BLOCKS-1){
      g_bar  = 0u;
      g_done = 0u;
      __threadfence();
    }
  }
}

extern "C" void kernel_launch(void* const* d_in, const int* in_sizes, int n_in,
                              void* d_out, int out_size)
{
  (void)in_sizes; (void)n_in; (void)out_size;
  const float* input = (const float*)d_in[0];
  const float* h0    = (const float*)d_in[1];
  const float* c0    = (const float*)d_in[2];
  const float* W_ih  = (const float*)d_in[3];
  const float* W_hh  = (const float*)d_in[4];
  const float* b_ih  = (const float*)d_in[5];
  const float* b_hh  = (const float*)d_in[6];
  float* out = (float*)d_out;

  xgates_gemm<<<dim3(16,1024), 256>>>(input, W_ih, b_ih, b_hh);

  cudaFuncSetAttribute(lstm_rec, cudaFuncAttributeMaxDynamicSharedMemorySize, REC_SMEM);
  lstm_rec<<<REC_BLOCKS, REC_THREADS, REC_SMEM>>>(h0, c0, W_hh, out);
}

// round 2
// speedup vs baseline: 1.1885x; 1.1885x over previous
#include <cuda_runtime.h>
#include <math.h>
#include <stdint.h>

#define T_STEPS 2048
#define BATCH   64
#define HID     256
#define GATE4   1024
#define NG      (BATCH*HID)          /* 16384 */
#define REC_BLOCKS 128
#define REC_THREADS 512
#define HPAD2   264                  /* padded row stride (floats) */

/* Scratch (device globals: no allocation allowed in kernel_launch) */
__device__ float g_xg[134217728];    /* [T][B][4H] precomputed input gates: 512 MB */
__device__ float g_h[2][NG];         /* double-buffered recurrent h, layout [b][j] */
__device__ unsigned g_bar;           /* monotonic grid barrier counter */
__device__ unsigned g_done;          /* end-of-kernel reset rendezvous */

__device__ __forceinline__ float dot4(float4 a, float4 b){
  return a.x*b.x + a.y*b.y + a.z*b.z + a.w*b.w;
}
__device__ __forceinline__ float fsigm(float x){          /* MUFU-based sigmoid */
  return __fdividef(1.f, 1.f + __expf(-x));
}
__device__ __forceinline__ float ftanh(float x){          /* tanh = 2*sigm(2x)-1 */
  return __fdividef(2.f, 1.f + __expf(-2.f*x)) - 1.f;
}

/* ---------------- Kernel A: x_gates = input @ W_ih^T + b_ih + b_hh ----------------
 * A: [M=131072, K=256], W: [N=1024, K=256]. BM=128, BN=64, BK=16; 256 thr;
 * TM=8 x TN=4 -> 32 acc/thread. FMA-bound at the fp32 SIMT roofline (~2.0ms). */
__global__ void __launch_bounds__(256, 2) xgates_gemm(
    const float* __restrict__ A, const float* __restrict__ W,
    const float* __restrict__ bih, const float* __restrict__ bhh)
{
  __shared__ float a_t[16][132];   /* [k][m], padded */
  __shared__ float b_t[16][68];    /* [k][n], padded */
  const int tid = threadIdx.x;
  const int bx = blockIdx.x, by = blockIdx.y;
  const int tx = tid & 15, ty = tid >> 4;

  float acc[8][4];
  #pragma unroll
  for (int m=0;m<8;m++)
    #pragma unroll
    for (int n=0;n<4;n++) acc[m][n]=0.f;

  const float* Ab = A + (size_t)by*128*256;
  const float* Wb = W + (size_t)bx*64*256;

  for (int kt=0; kt<16; ++kt){
    const int k0 = kt*16;
    #pragma unroll
    for (int r=0;r<2;r++){
      int idx = tid + r*256;
      int row = idx >> 2, kq = idx & 3;
      float4 v = *(const float4*)(Ab + (size_t)row*256 + k0 + kq*4);
      a_t[kq*4+0][row]=v.x; a_t[kq*4+1][row]=v.y;
      a_t[kq*4+2][row]=v.z; a_t[kq*4+3][row]=v.w;
    }
    {
      int n = tid >> 2, kq = tid & 3;
      float4 v = *(const float4*)(Wb + (size_t)n*256 + k0 + kq*4);
      b_t[kq*4+0][n]=v.x; b_t[kq*4+1][n]=v.y;
      b_t[kq*4+2][n]=v.z; b_t[kq*4+3][n]=v.w;
    }
    __syncthreads();
    #pragma unroll
    for (int k=0;k<16;k++){
      float af[8], bf[4];
      *(float4*)(af)   = *(const float4*)&a_t[k][ty*8];
      *(float4*)(af+4) = *(const float4*)&a_t[k][ty*8+4];
      *(float4*)(bf)   = *(const float4*)&b_t[k][tx*4];
      #pragma unroll
      for (int m=0;m<8;m++)
        #pragma unroll
        for (int n=0;n<4;n++)
          acc[m][n] += af[m]*bf[n];
    }
    __syncthreads();
  }

  const int gn = bx*64 + tx*4;
  const float bb0 = bih[gn+0]+bhh[gn+0];
  const float bb1 = bih[gn+1]+bhh[gn+1];
  const float bb2 = bih[gn+2]+bhh[gn+2];
  const float bb3 = bih[gn+3]+bhh[gn+3];
  #pragma unroll
  for (int m=0;m<8;m++){
    int gm = by*128 + ty*8 + m;
    float4 o = make_float4(acc[m][0]+bb0, acc[m][1]+bb1, acc[m][2]+bb2, acc[m][3]+bb3);
    *(float4*)(g_xg + (size_t)gm*GATE4 + gn) = o;
  }
}

/* ---------------- Kernel B: persistent recurrence ----------------
 * 128 blocks = 4 batch-groups x 32 j-groups. Block owns 16 batches x 8 hidden
 * units (32 gate-rows). 512 threads = 16 warps; warp owns 2 gate-rows.
 * Lane: lg = lane&15 (k-split over 16 lanes), hb = lane>>4 (batch pair bit).
 * W_hh slice in REGISTERS (32 floats/lane). Per step:
 *   stage 16 batches of h (2 LDG.128 + 2 STS.128 per thread, __ldcg),
 *   8 passes x (4 LDS.128 + 32 FFMA + 5 SHFL reduce),
 *   epilogue on 128 threads (MUFU activations, c in register),
 *   grid barrier with out-stores + x-gate prefetch in its shadow. */
__global__ void __launch_bounds__(REC_THREADS, 1) lstm_rec(
    const float* __restrict__ h0, const float* __restrict__ c0,
    const float* __restrict__ W_hh, float* __restrict__ out)
{
  __shared__ float h_sm[16*HPAD2];       /* [16 local batches][k], padded */
  __shared__ float gates_sm[32*16];      /* [local gate-row][local batch] */

  const int tid  = threadIdx.x;
  const int blk  = blockIdx.x;
  const int bgid = blk & 3;              /* batch group */
  const int jgid = blk >> 2;             /* hidden-unit group */
  const int b0   = bgid*16;
  const int j0   = jgid*8;

  const int wid  = tid >> 5, lane = tid & 31;
  const int lg   = lane & 15, hb = lane >> 4;
  const int rl0  = 2*wid;                /* local gate-rows owned by this warp */

  /* W_hh slice -> registers: wr[r][q] covers k = lg*4 + 64*q .. +3
   * local row rl -> global gate-row: (rl>>3)*256 + j0 + (rl&7)              */
  float4 wr0[4], wr1[4];
  {
    const int gr0 = ((rl0  )>>3)*HID + j0 + ((rl0  )&7);
    const int gr1 = ((rl0+1)>>3)*HID + j0 + ((rl0+1)&7);
    #pragma unroll
    for (int q=0;q<4;q++){
      wr0[q] = *(const float4*)(W_hh + (size_t)gr0*HID + lg*4 + 64*q);
      wr1[q] = *(const float4*)(W_hh + (size_t)gr1*HID + lg*4 + 64*q);
    }
  }

  /* epilogue ownership: tid<128 owns (bl = tid>>3, jl = tid&7) */
  const int jl = tid & 7, bl = (tid >> 3) & 15;
  const int eb = b0 + bl, ej = j0 + jl;
  float c_reg = 0.f, xg0=0.f, xg1=0.f, xg2=0.f, xg3=0.f;
  if (tid < 128){
    c_reg = c0[eb*HID + ej];
    const float* xp = g_xg + (size_t)eb*GATE4 + ej;   /* t = 0 */
    xg0 = xp[0]; xg1 = xp[HID]; xg2 = xp[2*HID]; xg3 = xp[3*HID];
  }

  for (int t=0; t<T_STEPS; ++t){
    /* ---- stage h: 16 batches, coalesced float4, __ldcg (L1 would be stale) */
    const float4* hsrc = (const float4*)(((t==0) ? h0 : g_h[t & 1]) + b0*HID);
    #pragma unroll
    for (int r=0;r<2;r++){
      int fi = tid + r*512;                  /* 0..1023 */
      int b = fi >> 6, c = fi & 63;
      float4 v = __ldcg(hsrc + b*64 + c);
      *(float4*)(h_sm + b*HPAD2 + c*4) = v;
    }
    __syncthreads();

    /* ---- compute: 8 passes of 2 batches (hb selects), 2 gate-rows per warp */
    #pragma unroll 2
    for (int p=0;p<8;p++){
      const int lb = p*2 + hb;
      const float* hr = h_sm + lb*HPAD2 + lg*4;
      float4 hv0 = *(const float4*)(hr);
      float4 hv1 = *(const float4*)(hr+64);
      float4 hv2 = *(const float4*)(hr+128);
      float4 hv3 = *(const float4*)(hr+192);
      float a0a = dot4(wr0[0],hv0) + dot4(wr0[1],hv1);
      float a0b = dot4(wr0[2],hv2) + dot4(wr0[3],hv3);
      float a1a = dot4(wr1[0],hv0) + dot4(wr1[1],hv1);
      float a1b = dot4(wr1[2],hv2) + dot4(wr1[3],hv3);
      float a0 = a0a + a0b;
      float a1 = a1a + a1b;
      /* reduce 2 values over 16 k-lanes: 5 SHFL total */
      a0 += __shfl_xor_sync(0xffffffffu, a0, 8);
      a1 += __shfl_xor_sync(0xffffffffu, a1, 8);
      float x = (lg & 8) ? a1 : a0;
      x += __shfl_xor_sync(0xffffffffu, x, 4);
      x += __shfl_xor_sync(0xffffffffu, x, 2);
      x += __shfl_xor_sync(0xffffffffu, x, 1);
      if ((lg & 7) == 0)
        gates_sm[(rl0 + (lg>>3))*16 + lb] = x;
    }
    __syncthreads();

    /* ---- epilogue: activations + state update (c stays in a register) */
    float hn = 0.f;
    if (tid < 128){
      float pi = gates_sm[(0*8+jl)*16 + bl] + xg0;
      float pf = gates_sm[(1*8+jl)*16 + bl] + xg1;
      float pg = gates_sm[(2*8+jl)*16 + bl] + xg2;
      float po = gates_sm[(3*8+jl)*16 + bl] + xg3;
      float ii = fsigm(pi), ff = fsigm(pf), gg = ftanh(pg), oo = fsigm(po);
      c_reg = ff*c_reg + ii*gg;
      hn = oo * ftanh(c_reg);
      g_h[(t+1)&1][eb*HID + ej] = hn;
    }
    __threadfence();
    __syncthreads();

    /* ---- grid barrier; out-stores + next x prefetch in the barrier shadow */
    if (tid == 0) atomicAdd(&g_bar, 1u);
    if (tid < 128){
      out[(size_t)t*NG + eb*HID + ej] = hn;
      if (t == T_STEPS-1){
        out[(size_t)T_STEPS*NG + eb*HID + ej]      = hn;     /* h_T */
        out[(size_t)T_STEPS*NG + NG + eb*HID + ej] = c_reg;  /* c_T */
      } else {
        const float* xp = g_xg + ((size_t)(t+1)*BATCH + eb)*GATE4 + ej;
        xg0 = xp[0]; xg1 = xp[HID]; xg2 = xp[2*HID]; xg3 = xp[3*HID];
      }
    }
    if (tid == 0){
      const unsigned target = (unsigned)(t+1) * REC_BLOCKS;
      while (*((volatile unsigned*)&g_bar) < target) { }
      __threadfence();
    }
    __syncthreads();
  }

  /* reset counters for the next graph replay: last block to arrive does it */
  if (tid == 0){
    unsigned prev = atomicAdd(&g_done, 1u);
    if (prev == REC_BLOCKS-1){
      g_bar  = 0u;
      g_done = 0u;
      __threadfence();
    }
  }
}

extern "C" void kernel_launch(void* const* d_in, const int* in_sizes, int n_in,
                              void* d_out, int out_size)
{
  (void)in_sizes; (void)n_in; (void)out_size;
  const float* input = (const float*)d_in[0];
  const float* h0    = (const float*)d_in[1];
  const float* c0    = (const float*)d_in[2];
  const float* W_ih  = (const float*)d_in[3];
  const float* W_hh  = (const float*)d_in[4];
  const float* b_ih  = (const float*)d_in[5];
  const float* b_hh  = (const float*)d_in[6];
  float* out = (float*)d_out;

  xgates_gemm<<<dim3(16,1024), 256>>>(input, W_ih, b_ih, b_hh);
  lstm_rec<<<REC_BLOCKS, REC_THREADS>>>(h0, c0, W_hh, out);
}

// round 3
// speedup vs baseline: 2.2942x; 1.9303x over previous
#include <cuda_runtime.h>
#include <math.h>
#include <stdint.h>

#define T_STEPS 2048
#define BATCH   64
#define HID     256
#define GATE4   1024
#define NG      (BATCH*HID)          /* 16384 */
#define REC_BLOCKS 128
#define REC_THREADS 512
#define GROUP_BLOCKS 32              /* blocks per batch-group barrier */
#define HPAD2   264                  /* padded h row stride (floats) */
#define GST     17                   /* gates_sm row stride */

/* Scratch (device globals: no allocation allowed in kernel_launch) */
__device__ float g_xg[134217728];    /* [T][B][4H] precomputed input gates */
__device__ float g_h[2][NG];         /* double-buffered recurrent h */
__device__ unsigned g_bar4[256];     /* 4 group barriers, 256B apart */
__device__ unsigned g_done;          /* end-of-kernel reset rendezvous */

__device__ __forceinline__ float dot4(float4 a, float4 b){
  return a.x*b.x + a.y*b.y + a.z*b.z + a.w*b.w;
}
__device__ __forceinline__ float fsigm(float x){
  return __fdividef(1.f, 1.f + __expf(-x));
}
__device__ __forceinline__ float ftanh(float x){
  return __fdividef(2.f, 1.f + __expf(-2.f*x)) - 1.f;
}
__device__ __forceinline__ unsigned ld_acq(const unsigned* p){
  unsigned v;
  asm volatile("ld.global.acquire.gpu.u32 %0, [%1];" : "=r"(v) : "l"(p) : "memory");
  return v;
}
__device__ __forceinline__ void red_rel_add(unsigned* p, unsigned v){
  asm volatile("red.release.gpu.global.add.u32 [%0], %1;" :: "l"(p), "r"(v) : "memory");
}

/* ---------------- Kernel A: x_gates = input @ W_ih^T + b_ih + b_hh ---------------- */
__global__ void __launch_bounds__(256, 2) xgates_gemm(
    const float* __restrict__ A, const float* __restrict__ W,
    const float* __restrict__ bih, const float* __restrict__ bhh)
{
  __shared__ float a_t[16][132];
  __shared__ float b_t[16][68];
  const int tid = threadIdx.x;
  const int bx = blockIdx.x, by = blockIdx.y;
  const int tx = tid & 15, ty = tid >> 4;

  float acc[8][4];
  #pragma unroll
  for (int m=0;m<8;m++)
    #pragma unroll
    for (int n=0;n<4;n++) acc[m][n]=0.f;

  const float* Ab = A + (size_t)by*128*256;
  const float* Wb = W + (size_t)bx*64*256;

  for (int kt=0; kt<16; ++kt){
    const int k0 = kt*16;
    #pragma unroll
    for (int r=0;r<2;r++){
      int idx = tid + r*256;
      int row = idx >> 2, kq = idx & 3;
      float4 v = *(const float4*)(Ab + (size_t)row*256 + k0 + kq*4);
      a_t[kq*4+0][row]=v.x; a_t[kq*4+1][row]=v.y;
      a_t[kq*4+2][row]=v.z; a_t[kq*4+3][row]=v.w;
    }
    {
      int n = tid >> 2, kq = tid & 3;
      float4 v = *(const float4*)(Wb + (size_t)n*256 + k0 + kq*4);
      b_t[kq*4+0][n]=v.x; b_t[kq*4+1][n]=v.y;
      b_t[kq*4+2][n]=v.z; b_t[kq*4+3][n]=v.w;
    }
    __syncthreads();
    #pragma unroll
    for (int k=0;k<16;k++){
      float af[8], bf[4];
      *(float4*)(af)   = *(const float4*)&a_t[k][ty*8];
      *(float4*)(af+4) = *(const float4*)&a_t[k][ty*8+4];
      *(float4*)(bf)   = *(const float4*)&b_t[k][tx*4];
      #pragma unroll
      for (int m=0;m<8;m++)
        #pragma unroll
        for (int n=0;n<4;n++)
          acc[m][n] += af[m]*bf[n];
    }
    __syncthreads();
  }

  const int gn = bx*64 + tx*4;
  const float bb0 = bih[gn+0]+bhh[gn+0];
  const float bb1 = bih[gn+1]+bhh[gn+1];
  const float bb2 = bih[gn+2]+bhh[gn+2];
  const float bb3 = bih[gn+3]+bhh[gn+3];
  #pragma unroll
  for (int m=0;m<8;m++){
    int gm = by*128 + ty*8 + m;
    float4 o = make_float4(acc[m][0]+bb0, acc[m][1]+bb1, acc[m][2]+bb2, acc[m][3]+bb3);
    *(float4*)(g_xg + (size_t)gm*GATE4 + gn) = o;
  }
}

/* ---------------- Kernel B: persistent recurrence ----------------
 * 128 blocks = 4 batch-groups x 32 j-groups; groups are INDEPENDENT chains
 * (gates for (b,j) need only h[b,:]), so each group has its own 32-block
 * barrier. Block: 16 batches x 8 hidden units = 32 gate-rows.
 * 512 threads = 16 warps = (8 row-quads) x (2 batch-halves).
 * Lane: lg = lane&15 (k-split), hb = lane>>4 (batch pair bit).
 * Warp holds 4 gate-rows of W_hh in registers (64 floats/lane).
 * Per step per thread: 2 LDG.128 stage, 4 passes x (4 LDS.128 + 64 FMA +
 * 8 SHFL), epilogue on 128 threads, release-red + acquire-poll barrier. */
__global__ void __launch_bounds__(REC_THREADS, 1) lstm_rec(
    const float* __restrict__ h0, const float* __restrict__ c0,
    const float* __restrict__ W_hh, float* __restrict__ out)
{
  __shared__ float h_sm[16*HPAD2];
  __shared__ float gates_sm[32*GST];

  const int tid  = threadIdx.x;
  const int blk  = blockIdx.x;
  const int bgid = blk & 3;
  const int jgid = blk >> 2;
  const int b0   = bgid*16;
  const int j0   = jgid*8;
  unsigned* barp = &g_bar4[bgid*64];

  const int wid  = tid >> 5, lane = tid & 31;
  const int lg   = lane & 15, hb = lane >> 4;
  const int wbh  = wid & 1;              /* batch half: local batches 8*wbh.. */
  const int rq   = wid >> 1;             /* row quad: local rows 4*rq..4*rq+3 */

  /* W_hh rows -> registers. local row rl: gate = rl>>3, j = j0 + (rl&7). */
  float4 wr[4][4];
  #pragma unroll
  for (int r=0;r<4;r++){
    const int rl = 4*rq + r;
    const int grow = (rl>>3)*HID + j0 + (rl&7);
    #pragma unroll
    for (int q=0;q<4;q++)
      wr[r][q] = *(const float4*)(W_hh + (size_t)grow*HID + lg*4 + 64*q);
  }

  /* epilogue ownership: tid<128 owns (bl = tid>>3, jl = tid&7) */
  const int jl = tid & 7, bl = (tid >> 3) & 15;
  const int eb = b0 + bl, ej = j0 + jl;
  float c_reg = 0.f, xg0=0.f, xg1=0.f, xg2=0.f, xg3=0.f;
  if (tid < 128){
    c_reg = c0[eb*HID + ej];
    const float* xp = g_xg + (size_t)eb*GATE4 + ej;   /* t = 0 */
    xg0 = xp[0]; xg1 = xp[HID]; xg2 = xp[2*HID]; xg3 = xp[3*HID];
  }

  for (int t=0; t<T_STEPS; ++t){
    /* ---- wait for previous step's h from this batch-group (acquire) */
    if (t){
      const unsigned target = (unsigned)t * GROUP_BLOCKS;
      while (ld_acq(barp) < target) { }
    }

    /* ---- stage h: 16 batches, coalesced float4, .cg (L1 would be stale) */
    const float4* hsrc = (const float4*)(((t==0) ? h0 : g_h[t & 1]) + b0*HID);
    #pragma unroll
    for (int r=0;r<2;r++){
      int fi = tid + r*512;
      int b = fi >> 6, c = fi & 63;
      float4 v = __ldcg(hsrc + b*64 + c);
      *(float4*)(h_sm + b*HPAD2 + c*4) = v;
    }
    __syncthreads();

    /* ---- compute: 4 passes of 2 batches; 4 gate-rows per warp */
    #pragma unroll
    for (int p=0;p<4;p++){
      const int lb = wbh*8 + p*2 + hb;
      const float* hr = h_sm + lb*HPAD2 + lg*4;
      float4 hv0 = *(const float4*)(hr);
      float4 hv1 = *(const float4*)(hr+64);
      float4 hv2 = *(const float4*)(hr+128);
      float4 hv3 = *(const float4*)(hr+192);
      float v0 = dot4(wr[0][0],hv0)+dot4(wr[0][1],hv1)+dot4(wr[0][2],hv2)+dot4(wr[0][3],hv3);
      float v1 = dot4(wr[1][0],hv0)+dot4(wr[1][1],hv1)+dot4(wr[1][2],hv2)+dot4(wr[1][3],hv3);
      float v2 = dot4(wr[2][0],hv0)+dot4(wr[2][1],hv1)+dot4(wr[2][2],hv2)+dot4(wr[2][3],hv3);
      float v3 = dot4(wr[3][0],hv0)+dot4(wr[3][1],hv1)+dot4(wr[3][2],hv2)+dot4(wr[3][3],hv3);
      /* reduce 4 rows over 16 k-lanes: 8 SHFL (lane bit4 = hb untouched) */
      v0 += __shfl_xor_sync(0xffffffffu, v0, 8);
      v1 += __shfl_xor_sync(0xffffffffu, v1, 8);
      v2 += __shfl_xor_sync(0xffffffffu, v2, 8);
      v3 += __shfl_xor_sync(0xffffffffu, v3, 8);
      float a = (lg & 8) ? v1 : v0;
      float b = (lg & 8) ? v3 : v2;
      a += __shfl_xor_sync(0xffffffffu, a, 4);
      b += __shfl_xor_sync(0xffffffffu, b, 4);
      float x = (lg & 4) ? b : a;
      x += __shfl_xor_sync(0xffffffffu, x, 2);
      x += __shfl_xor_sync(0xffffffffu, x, 1);
      if ((lg & 3) == 0){
        const int rsel = ((lg>>3)&1) | (((lg>>2)&1)<<1);   /* 0,8,4,12 -> 0,1,2,3 */
        gates_sm[(4*rq + rsel)*GST + lb] = x;
      }
    }
    __syncthreads();

    /* ---- epilogue: activations + state update (c stays in a register) */
    float hn = 0.f;
    if (tid < 128){
      float pi = gates_sm[(0*8+jl)*GST + bl] + xg0;
      float pf = gates_sm[(1*8+jl)*GST + bl] + xg1;
      float pg = gates_sm[(2*8+jl)*GST + bl] + xg2;
      float po = gates_sm[(3*8+jl)*GST + bl] + xg3;
      float ii = fsigm(pi), ff = fsigm(pf), gg = ftanh(pg), oo = fsigm(po);
      c_reg = ff*c_reg + ii*gg;
      hn = oo * ftanh(c_reg);
      __stcg(&g_h[(t+1)&1][eb*HID + ej], hn);
    }
    __syncthreads();   /* h stores observed CTA-wide before tid0's release */

    /* ---- arrival (release), then out-stores + prefetch in its shadow */
    if (tid == 0) red_rel_add(barp, 1u);
    if (tid < 128){
      out[(size_t)t*NG + eb*HID + ej] = hn;
      if (t == T_STEPS-1){
        out[(size_t)T_STEPS*NG + eb*HID + ej]      = hn;     /* h_T */
        out[(size_t)T_STEPS*NG + NG + eb*HID + ej] = c_reg;  /* c_T */
      } else {
        const float* xp = g_xg + ((size_t)(t+1)*BATCH + eb)*GATE4 + ej;
        xg0 = xp[0]; xg1 = xp[HID]; xg2 = xp[2*HID]; xg3 = xp[3*HID];
      }
    }
  }

  /* reset counters for the next graph replay: last block to arrive does it */
  if (tid == 0){
    __threadfence();
    unsigned prev = atomicAdd(&g_done, 1u);
    if (prev == REC_BLOCKS-1){
      g_bar4[0] = 0u; g_bar4[64] = 0u; g_bar4[128] = 0u; g_bar4[192] = 0u;
      g_done = 0u;
      __threadfence();
    }
  }
}

extern "C" void kernel_launch(void* const* d_in, const int* in_sizes, int n_in,
                              void* d_out, int out_size)
{
  (void)in_sizes; (void)n_in; (void)out_size;
  const float* input = (const float*)d_in[0];
  const float* h0    = (const float*)d_in[1];
  const float* c0    = (const float*)d_in[2];
  const float* W_ih  = (const float*)d_in[3];
  const float* W_hh  = (const float*)d_in[4];
  const float* b_ih  = (const float*)d_in[5];
  const float* b_hh  = (const float*)d_in[6];
  float* out = (float*)d_out;

  xgates_gemm<<<dim3(16,1024), 256>>>(input, W_ih, b_ih, b_hh);
  lstm_rec<<<REC_BLOCKS, REC_THREADS>>>(h0, c0, W_hh, out);
}